// round 1
// baseline (speedup 1.0000x reference)
#include <cuda_runtime.h>

#define NV   2562
#define DEG  8
#define FIN  8
#define FOUT 16
#define KCH  5
#define SP   512                 // spatial = X*Y*Z
#define SP4  (SP/4)              // 128 float4 per (v,f) row-chunk
#define DD   (FIN*SP)            // 4096 floats per vertex row
#define DD4  (DD/4)              // 1024 float4

// Scratch: 3 rolling Chebyshev levels (x1, x2, x3), 42 MB each.
__device__ float4 g_buf[3][(size_t)NV * DD4];

// One block per vertex v; 128 threads cover the 512 spatial floats as float4.
// x_next[v,f,s] = (has_prev ? 2*spmv - prev : spmv)
__global__ __launch_bounds__(SP4) void spmv_step_kernel(
    const float4* __restrict__ cur,  int cvs4, int cfs4,   // strides in float4 units
    const float4* __restrict__ prev, int pvs4, int pfs4,
    float4* __restrict__ next,
    const int* __restrict__ cols, const float* __restrict__ vals,
    int has_prev)
{
    __shared__ int   scol[DEG];
    __shared__ float sval[DEG];
    const int v = blockIdx.x;
    const int t = threadIdx.x;
    if (t < DEG) {
        scol[t] = cols[v * DEG + t];
        sval[t] = vals[v * DEG + t];
    }
    __syncthreads();

    #pragma unroll
    for (int f = 0; f < FIN; ++f) {
        float4 acc = make_float4(0.f, 0.f, 0.f, 0.f);
        #pragma unroll
        for (int n = 0; n < DEG; ++n) {
            const float4 x = cur[(size_t)scol[n] * cvs4 + f * cfs4 + t];
            const float  w = sval[n];
            acc.x += w * x.x; acc.y += w * x.y;
            acc.z += w * x.z; acc.w += w * x.w;
        }
        if (has_prev) {
            const float4 p = prev[(size_t)v * pvs4 + f * pfs4 + t];
            acc.x = 2.f * acc.x - p.x; acc.y = 2.f * acc.y - p.y;
            acc.z = 2.f * acc.z - p.z; acc.w = 2.f * acc.w - p.w;
        }
        next[(size_t)v * DD4 + f * SP4 + t] = acc;
    }
}

// Last SpMV (x4) fused with the (K,FIN)->(FOUT) contraction + bias.
// x0 = inputs (native [f,v,s] layout), x1..x3 in scratch ([v,f,s] layout).
__global__ __launch_bounds__(SP4) void final_kernel(
    const float4* __restrict__ x0,
    const float4* __restrict__ x1,
    const float4* __restrict__ x2,
    const float4* __restrict__ x3,
    const int* __restrict__ cols, const float* __restrict__ vals,
    const float* __restrict__ weight, const float* __restrict__ bias,
    float4* __restrict__ out)
{
    __shared__ int   scol[DEG];
    __shared__ float sval[DEG];
    __shared__ float sw[KCH * FIN * FOUT];   // 640 floats, [k][f][o]
    __shared__ float sb[FOUT];

    const int v = blockIdx.x;
    const int t = threadIdx.x;
    if (t < DEG) {
        scol[t] = cols[v * DEG + t];
        sval[t] = vals[v * DEG + t];
    }
    for (int i = t; i < KCH * FIN * FOUT; i += blockDim.x) sw[i] = weight[i];
    if (t < FOUT) sb[t] = bias[t];
    __syncthreads();

    float4 c[FOUT];
    #pragma unroll
    for (int o = 0; o < FOUT; ++o)
        c[o] = make_float4(sb[o], sb[o], sb[o], sb[o]);

    #pragma unroll
    for (int f = 0; f < FIN; ++f) {
        // x4[v,f,s] = 2 * spmv(x3) - x2
        float4 acc = make_float4(0.f, 0.f, 0.f, 0.f);
        #pragma unroll
        for (int n = 0; n < DEG; ++n) {
            const float4 x = x3[(size_t)scol[n] * DD4 + f * SP4 + t];
            const float  w = sval[n];
            acc.x += w * x.x; acc.y += w * x.y;
            acc.z += w * x.z; acc.w += w * x.w;
        }
        const float4 p2 = x2[(size_t)v * DD4 + f * SP4 + t];
        float4 x4f;
        x4f.x = 2.f * acc.x - p2.x; x4f.y = 2.f * acc.y - p2.y;
        x4f.z = 2.f * acc.z - p2.z; x4f.w = 2.f * acc.w - p2.w;

        const float4 x0f = x0[(size_t)f * (NV * SP4) + (size_t)v * SP4 + t];
        const float4 x1f = x1[(size_t)v * DD4 + f * SP4 + t];
        const float4 x3f = x3[(size_t)v * DD4 + f * SP4 + t];

        #pragma unroll
        for (int o = 0; o < FOUT; ++o) {
            const float w0 = sw[0 * FIN * FOUT + f * FOUT + o];
            const float w1 = sw[1 * FIN * FOUT + f * FOUT + o];
            const float w2 = sw[2 * FIN * FOUT + f * FOUT + o];
            const float w3 = sw[3 * FIN * FOUT + f * FOUT + o];
            const float w4 = sw[4 * FIN * FOUT + f * FOUT + o];
            c[o].x += x0f.x*w0 + x1f.x*w1 + p2.x*w2 + x3f.x*w3 + x4f.x*w4;
            c[o].y += x0f.y*w0 + x1f.y*w1 + p2.y*w2 + x3f.y*w3 + x4f.y*w4;
            c[o].z += x0f.z*w0 + x1f.z*w1 + p2.z*w2 + x3f.z*w3 + x4f.z*w4;
            c[o].w += x0f.w*w0 + x1f.w*w1 + p2.w*w2 + x3f.w*w3 + x4f.w*w4;
        }
    }

    #pragma unroll
    for (int o = 0; o < FOUT; ++o)
        out[(size_t)o * (NV * SP4) + (size_t)v * SP4 + t] = c[o];
}

extern "C" void kernel_launch(void* const* d_in, const int* in_sizes, int n_in,
                              void* d_out, int out_size) {
    const float* inputs = (const float*)d_in[0];
    // d_in[1] = lap_rows (unused: rows are repeat(arange(V), DEG) by construction)
    const int*   cols   = (const int*)d_in[2];
    const float* vals   = (const float*)d_in[3];
    const float* weight = (const float*)d_in[4];
    const float* bias   = (const float*)d_in[5];
    float4*      out    = (float4*)d_out;

    void* sym = nullptr;
    cudaGetSymbolAddress(&sym, g_buf);
    float4* g0 = (float4*)sym;
    float4* g1 = g0 + (size_t)NV * DD4;
    float4* g2 = g1 + (size_t)NV * DD4;

    const float4* in4 = (const float4*)inputs;
    const int IVS4 = SP4;            // input vertex stride (float4)
    const int IFS4 = NV * SP4;       // input feature stride (float4)

    // x1 = L @ x0 (x0 read directly from inputs layout)
    spmv_step_kernel<<<NV, SP4>>>(in4, IVS4, IFS4, nullptr, 0, 0,
                                  g0, cols, vals, 0);
    // x2 = 2 L x1 - x0
    spmv_step_kernel<<<NV, SP4>>>(g0, DD4, SP4, in4, IVS4, IFS4,
                                  g1, cols, vals, 1);
    // x3 = 2 L x2 - x1
    spmv_step_kernel<<<NV, SP4>>>(g1, DD4, SP4, g0, DD4, SP4,
                                  g2, cols, vals, 1);
    // x4 (in registers) + einsum over (k,f) + bias -> out
    final_kernel<<<NV, SP4>>>(in4, g0, g1, g2, cols, vals, weight, bias, out);
}